// round 4
// baseline (speedup 1.0000x reference)
#include <cuda_runtime.h>
#include <cstdint>

#define B_    4
#define N_    1000
#define T_    12
#define D_    64
#define HID_  128
#define EF_   64
#define E_    64000
#define SEG_  (B_*N_)       // 4000
#define ROWS_ (SEG_*T_)     // 48000
#define TD_   (T_*D_)       // 768
#define TH_   (T_*HID_)     // 1536

typedef unsigned long long u64;

// ---------------- device scratch ----------------
__device__ float g_S1[ROWS_ * HID_];
__device__ float g_S2[ROWS_ * HID_];
__device__ int   g_cnt[2 * SEG_];
__device__ int   g_off[2 * (SEG_ + 1)];
__device__ int   g_cur[2 * SEG_];
__device__ int   g_csr_s[E_];
__device__ int   g_csr_r[E_];

// ---------------- f32x2 packed helpers ----------------
__device__ __forceinline__ void fma2(u64 &d, u64 a, u64 b) {
    asm("fma.rn.f32x2 %0, %1, %2, %0;" : "+l"(d) : "l"(a), "l"(b));
}
__device__ __forceinline__ u64 pack2(float x, float y) {
    u64 r; asm("mov.b64 %0, {%1, %2};" : "=l"(r) : "f"(x), "f"(y)); return r;
}
__device__ __forceinline__ float2 unpack2(u64 v) {
    float2 r; asm("mov.b64 {%0, %1}, %2;" : "=f"(r.x), "=f"(r.y) : "l"(v)); return r;
}

// ---------------- CSR build ----------------
__global__ void k_zero() {
    int i = blockIdx.x * blockDim.x + threadIdx.x;
    if (i < 2 * SEG_) g_cnt[i] = 0;
}

__global__ void k_count(const int* __restrict__ bi, const int* __restrict__ si,
                        const int* __restrict__ ri) {
    int e = blockIdx.x * blockDim.x + threadIdx.x;
    if (e >= E_) return;
    int b = bi[e];
    atomicAdd(&g_cnt[b * N_ + si[e]], 1);
    atomicAdd(&g_cnt[SEG_ + b * N_ + ri[e]], 1);
}

// exclusive scan of 4000 counts; blockIdx.x selects send(0)/recv(1)
__global__ void k_scan2() {
    int which = blockIdx.x;
    const int* cnt = g_cnt + which * SEG_;
    int* off = g_off + which * (SEG_ + 1);
    int* cur = g_cur + which * SEG_;
    __shared__ int part[1024];
    int tid = threadIdx.x;
    int l[4]; int s = 0;
#pragma unroll
    for (int j = 0; j < 4; j++) {
        int idx = tid * 4 + j;
        l[j] = (idx < SEG_) ? cnt[idx] : 0;
        s += l[j];
    }
    part[tid] = s;
    __syncthreads();
    for (int o = 1; o < 1024; o <<= 1) {
        int v = part[tid];
        int a = (tid >= o) ? part[tid - o] : 0;
        __syncthreads();
        part[tid] = v + a;
        __syncthreads();
    }
    int run = (tid > 0) ? part[tid - 1] : 0;
#pragma unroll
    for (int j = 0; j < 4; j++) {
        int idx = tid * 4 + j;
        if (idx < SEG_) { off[idx] = run; cur[idx] = run; run += l[j]; }
    }
    if (tid == 1023) off[SEG_] = part[1023];
}

__global__ void k_scatter(const int* __restrict__ bi, const int* __restrict__ si,
                          const int* __restrict__ ri) {
    int e = blockIdx.x * blockDim.x + threadIdx.x;
    if (e >= E_) return;
    int b = bi[e];
    int ps = atomicAdd(&g_cur[b * N_ + si[e]], 1);
    g_csr_s[ps] = e;
    int pr = atomicAdd(&g_cur[SEG_ + b * N_ + ri[e]], 1);
    g_csr_r[pr] = e;
}

// ---------------- node projection ----------------
#define NP_SMEM_FLOATS (8192 + 8192 + 512)
__global__ void k_nodeproj(const float* __restrict__ x,
                           const float* __restrict__ A1w, const float* __restrict__ A1b,
                           const float* __restrict__ A2w, const float* __restrict__ A2b) {
    extern __shared__ float shp[];
    float* A1sh = shp;
    float* A2sh = shp + 8192;
    float* xsh  = shp + 16384;
    int tid = threadIdx.x;
    {
        float4* d1 = (float4*)A1sh; const float4* s1 = (const float4*)A1w;
        for (int i = tid; i < 2048; i += 128) d1[i] = s1[i];
        float4* d2 = (float4*)A2sh; const float4* s2 = (const float4*)A2w;
        for (int i = tid; i < 2048; i += 128) d2[i] = s2[i];
    }
    float b12 = A1b[tid] + A2b[tid];
    int rowBase = blockIdx.x * 128;
    for (int p = 0; p < 16; p++) {
        int r0 = rowBase + p * 8;
        __syncthreads();
        for (int i = tid; i < 512; i += 128) xsh[i] = x[(size_t)r0 * 64 + i];
        __syncthreads();
        float a1[8], a2[8];
#pragma unroll
        for (int r = 0; r < 8; r++) { a1[r] = b12; a2[r] = 0.f; }
#pragma unroll 4
        for (int d = 0; d < 64; d++) {
            float w1 = A1sh[d * 128 + tid];
            float w2 = A2sh[d * 128 + tid];
#pragma unroll
            for (int r = 0; r < 8; r++) {
                float xv = xsh[r * 64 + d];
                a1[r] = fmaf(xv, w1, a1[r]);
                a2[r] = fmaf(xv, w2, a2[r]);
            }
        }
#pragma unroll
        for (int r = 0; r < 8; r++) {
            g_S1[(size_t)(r0 + r) * 128 + tid] = a1[r];
            g_S2[(size_t)(r0 + r) * 128 + tid] = a2[r];
        }
    }
}

// ---------------- fused edge MLP + segment softmax ----------------
// One block per sender segment. 384 threads = 24 half-warp groups of 16; each
// group owns one edge per batch. Time-paired f32x2 accumulation (t,t+1 in
// halves), 4 cols/thread. No block syncs in the hot loop.
#define OFF_A3   0
#define OFF_A4   8192
#define OFF_S1   12288
#define OFF_S2   13824
#define OFF_SLOT 15360
#define SLOT_STRIDE 1552                    // floats; 1552 % 32 == 16
#define FK_SMEM_FLOATS (OFF_SLOT + 24 * SLOT_STRIDE)   // 52608 floats = 210,432 B

__global__ void __launch_bounds__(384, 1)
k_fused(const int* __restrict__ bi, const int* __restrict__ ri,
        const float* __restrict__ A3w, const float* __restrict__ A4w,
        const float* __restrict__ A4b, float* __restrict__ outv) {
    extern __shared__ float sh[];
    int tid = threadIdx.x;
    int seg = blockIdx.x;

    // stage weights + sender rows
    {
        float4* d3 = (float4*)(sh + OFF_A3); const float4* s3 = (const float4*)A3w;
        for (int i = tid; i < 2048; i += 384) d3[i] = s3[i];
        float4* d4 = (float4*)(sh + OFF_A4); const float4* s4 = (const float4*)A4w;
        for (int i = tid; i < 1024; i += 384) d4[i] = s4[i];
        const float4* g1 = (const float4*)(g_S1 + (size_t)seg * TH_);
        const float4* g2 = (const float4*)(g_S2 + (size_t)seg * TH_);
        float4* S1s4 = (float4*)(sh + OFF_S1);
        float4* S2s4 = (float4*)(sh + OFF_S2);
        for (int i = tid; i < 384; i += 384) { S1s4[i] = g1[i]; S2s4[i] = g2[i]; }
    }
    int beg = g_off[seg], end = g_off[seg + 1];
    __syncthreads();
    if (beg == end) return;

    int lane = tid & 31;
    int wrp  = tid >> 5;          // 0..11
    int half = lane >> 4;         // 0/1
    int lp   = lane & 15;         // 0..15
    int slot = wrp * 2 + half;    // 0..23
    int c0   = lp * 4;            // 4 adjacent output cols

    float* myslot = sh + OFF_SLOT + slot * SLOT_STRIDE;
    float2* htp2 = (float2*)myslot;           // [6][128] f2 pairs, idx 16*(k%8)+k/8
    float2* dtp2 = (float2*)myslot;           // overlay: [6][64] f2, idx 16*(kk%4)+kk/4
    const float4* A3sh4 = (const float4*)(sh + OFF_A3);
    const float4* A4sh4 = (const float4*)(sh + OFF_A4);
    const float4* S1s4  = (const float4*)(sh + OFF_S1);
    const float4* S2s4  = (const float4*)(sh + OFF_S2);
    float4 bias = ((const float4*)A4b)[lp];

    int nbat = (end - beg + 23) / 24;
    for (int b = 0; b < nbat; b++) {
        int i = beg + b * 24 + slot;
        bool valid = (i < end);
        int e = 0;
        const float4 *r1 = 0, *r2 = 0;
        if (valid) {
            e = g_csr_s[i];
            int nr = bi[e] * N_ + ri[e];
            r1 = (const float4*)(g_S1 + (size_t)nr * TH_);
            r2 = (const float4*)(g_S2 + (size_t)nr * TH_);
            // hdiff: thread owns k = 8*lp .. 8*lp+7, time-paired
#pragma unroll
            for (int p = 0; p < 6; p++) {
                int i0 = (2 * p) * 32 + lp * 2;       // float4 index, t0
                int i1 = i0 + 32;                      // t1
                float h0v[8], h1v[8];
                {
                    float4 Aa = S1s4[i0], Ab = S1s4[i0 + 1];
                    float4 Ba = r2[i0],   Bb = r2[i0 + 1];
                    float4 Ca = r1[i0],   Cb = r1[i0 + 1];
                    float4 Da = S2s4[i0], Db = S2s4[i0 + 1];
                    h0v[0]=fmaxf(Aa.x+Ba.x,0.f)-fmaxf(Ca.x+Da.x,0.f);
                    h0v[1]=fmaxf(Aa.y+Ba.y,0.f)-fmaxf(Ca.y+Da.y,0.f);
                    h0v[2]=fmaxf(Aa.z+Ba.z,0.f)-fmaxf(Ca.z+Da.z,0.f);
                    h0v[3]=fmaxf(Aa.w+Ba.w,0.f)-fmaxf(Ca.w+Da.w,0.f);
                    h0v[4]=fmaxf(Ab.x+Bb.x,0.f)-fmaxf(Cb.x+Db.x,0.f);
                    h0v[5]=fmaxf(Ab.y+Bb.y,0.f)-fmaxf(Cb.y+Db.y,0.f);
                    h0v[6]=fmaxf(Ab.z+Bb.z,0.f)-fmaxf(Cb.z+Db.z,0.f);
                    h0v[7]=fmaxf(Ab.w+Bb.w,0.f)-fmaxf(Cb.w+Db.w,0.f);
                }
                {
                    float4 Aa = S1s4[i1], Ab = S1s4[i1 + 1];
                    float4 Ba = r2[i1],   Bb = r2[i1 + 1];
                    float4 Ca = r1[i1],   Cb = r1[i1 + 1];
                    float4 Da = S2s4[i1], Db = S2s4[i1 + 1];
                    h1v[0]=fmaxf(Aa.x+Ba.x,0.f)-fmaxf(Ca.x+Da.x,0.f);
                    h1v[1]=fmaxf(Aa.y+Ba.y,0.f)-fmaxf(Ca.y+Da.y,0.f);
                    h1v[2]=fmaxf(Aa.z+Ba.z,0.f)-fmaxf(Ca.z+Da.z,0.f);
                    h1v[3]=fmaxf(Aa.w+Ba.w,0.f)-fmaxf(Ca.w+Da.w,0.f);
                    h1v[4]=fmaxf(Ab.x+Bb.x,0.f)-fmaxf(Cb.x+Db.x,0.f);
                    h1v[5]=fmaxf(Ab.y+Bb.y,0.f)-fmaxf(Cb.y+Db.y,0.f);
                    h1v[6]=fmaxf(Ab.z+Bb.z,0.f)-fmaxf(Cb.z+Db.z,0.f);
                    h1v[7]=fmaxf(Ab.w+Bb.w,0.f)-fmaxf(Cb.w+Db.w,0.f);
                }
#pragma unroll
                for (int q = 0; q < 8; q++)            // k = 8*lp+q -> idx 16*q + lp
                    htp2[p * 128 + 16 * q + lp] = make_float2(h0v[q], h1v[q]);
            }
        }
        __syncwarp();

        if (valid) {
            // GEMM1: acc[j][p] pairs over k=0..127
            u64 acc[4][6];
#pragma unroll
            for (int j = 0; j < 4; j++)
#pragma unroll
                for (int p = 0; p < 6; p++) acc[j][p] = 0ull;
            for (int aa = 0; aa < 16; aa++) {
#pragma unroll
                for (int ii = 0; ii < 8; ii++) {
                    int k = aa * 8 + ii;
                    float4 w = A3sh4[k * 16 + lp];
                    u64 w0 = pack2(w.x, w.x), w1 = pack2(w.y, w.y);
                    u64 w2 = pack2(w.z, w.z), w3 = pack2(w.w, w.w);
#pragma unroll
                    for (int p = 0; p < 6; p++) {
                        u64 h = *(const u64*)&htp2[p * 128 + 16 * ii + aa];
                        fma2(acc[0][p], w0, h);
                        fma2(acc[1][p], w1, h);
                        fma2(acc[2][p], w2, h);
                        fma2(acc[3][p], w3, h);
                    }
                }
            }
            __syncwarp();
            // relu + store d pairs: col kk = c0+j -> idx 16*(kk%4)+kk/4 = 16*j+lp
#pragma unroll
            for (int p = 0; p < 6; p++)
#pragma unroll
                for (int j = 0; j < 4; j++) {
                    float2 v = unpack2(acc[j][p]);
                    *(u64*)&dtp2[p * 64 + 16 * j + lp] =
                        pack2(fmaxf(v.x, 0.f), fmaxf(v.y, 0.f));
                }
        } else {
            __syncwarp();
        }
        __syncwarp();

        if (valid) {
            // GEMM2 over kk=0..63
            u64 vac[4][6];
#pragma unroll
            for (int j = 0; j < 4; j++)
#pragma unroll
                for (int p = 0; p < 6; p++) vac[j][p] = 0ull;
            for (int a = 0; a < 16; a++) {
#pragma unroll
                for (int bq = 0; bq < 4; bq++) {
                    int kk = a * 4 + bq;
                    float4 w = A4sh4[kk * 16 + lp];
                    u64 w0 = pack2(w.x, w.x), w1 = pack2(w.y, w.y);
                    u64 w2 = pack2(w.z, w.z), w3 = pack2(w.w, w.w);
#pragma unroll
                    for (int p = 0; p < 6; p++) {
                        u64 d = *(const u64*)&dtp2[p * 64 + 16 * bq + a];
                        fma2(vac[0][p], w0, d);
                        fma2(vac[1][p], w1, d);
                        fma2(vac[2][p], w2, d);
                        fma2(vac[3][p], w3, d);
                    }
                }
            }
            // epilogue: bias + STG.128 per time row
            float* ebase = outv + (size_t)e * TD_;
#pragma unroll
            for (int p = 0; p < 6; p++) {
                float2 v0 = unpack2(vac[0][p]);
                float2 v1 = unpack2(vac[1][p]);
                float2 v2 = unpack2(vac[2][p]);
                float2 v3 = unpack2(vac[3][p]);
                float4 r0 = make_float4(v0.x + bias.x, v1.x + bias.y,
                                        v2.x + bias.z, v3.x + bias.w);
                float4 r1o = make_float4(v0.y + bias.x, v1.y + bias.y,
                                         v2.y + bias.z, v3.y + bias.w);
                *(float4*)(ebase + (2 * p) * 64 + c0) = r0;
                *(float4*)(ebase + (2 * p + 1) * 64 + c0) = r1o;
            }
        }
        __syncwarp();
    }

    // ---- segment softmax: 3 L2-hot passes, 2 adjacent cols per thread ----
    __syncthreads();
    int c = 2 * tid;             // 0..766
    float m0 = -1e30f, m1 = -1e30f;
    for (int i = beg; i < end; i++) {
        const float2 v = *(const float2*)(outv + (size_t)g_csr_s[i] * TD_ + c);
        m0 = fmaxf(m0, v.x); m1 = fmaxf(m1, v.y);
    }
    float s0 = 0.f, s1 = 0.f;
    for (int i = beg; i < end; i++) {
        const float2 v = *(const float2*)(outv + (size_t)g_csr_s[i] * TD_ + c);
        s0 += __expf(v.x - m0); s1 += __expf(v.y - m1);
    }
    float r0 = 1.f / (s0 + 1e-12f), r1 = 1.f / (s1 + 1e-12f);
    for (int i = beg; i < end; i++) {
        float2* vp = (float2*)(outv + (size_t)g_csr_s[i] * TD_ + c);
        float2 v = *vp;
        v.x = __expf(v.x - m0) * r0;
        v.y = __expf(v.y - m1) * r1;
        *vp = v;
    }
}

// ---------------- per-receiver aggregation + x update ----------------
__global__ void k_aggregate(const float* __restrict__ x, const float* __restrict__ v,
                            const int* __restrict__ bi, const int* __restrict__ si,
                            float* __restrict__ outx) {
    int seg = blockIdx.x;
    int tid = threadIdx.x;
    int beg = g_off[(SEG_ + 1) + seg], end = g_off[(SEG_ + 1) + seg + 1];
    int c0 = tid, c1 = tid + 256, c2 = tid + 512;
    float a0 = 0.f, a1 = 0.f, a2 = 0.f;
    for (int i = beg; i < end; i++) {
        int e = g_csr_r[i];
        int ns = bi[e] * N_ + si[e];
        const float* vp = v + (size_t)e * TD_;
        const float* xs = x + (size_t)ns * TD_;
        a0 = fmaf(vp[c0], xs[c0], a0);
        a1 = fmaf(vp[c1], xs[c1], a1);
        a2 = fmaf(vp[c2], xs[c2], a2);
    }
    const float* xr = x + (size_t)seg * TD_;
    float* o = outx + (size_t)seg * TD_;
    o[c0] = xr[c0] + 0.1f * (a0 - xr[c0]);
    o[c1] = xr[c1] + 0.1f * (a1 - xr[c1]);
    o[c2] = xr[c2] + 0.1f * (a2 - xr[c2]);
}

// ---------------- launch ----------------
extern "C" void kernel_launch(void* const* d_in, const int* in_sizes, int n_in,
                              void* d_out, int out_size) {
    const float* x   = (const float*)d_in[0];
    const int*   bi  = (const int*)d_in[1];
    const int*   si  = (const int*)d_in[2];
    const int*   ri  = (const int*)d_in[3];
    const float* A1w = (const float*)d_in[4];
    const float* A1b = (const float*)d_in[5];
    const float* A2w = (const float*)d_in[6];
    const float* A2b = (const float*)d_in[7];
    const float* A3w = (const float*)d_in[8];
    // d_in[9] = A3_b: cancels in z_ij - z_ji
    const float* A4w = (const float*)d_in[10];
    const float* A4b = (const float*)d_in[11];

    float* outx = (float*)d_out;
    float* outv = outx + (size_t)ROWS_ * D_;

    const int np_smem = NP_SMEM_FLOATS * 4;
    const int fk_smem = FK_SMEM_FLOATS * 4;    // 210,432 B
    cudaFuncSetAttribute(k_nodeproj, cudaFuncAttributeMaxDynamicSharedMemorySize, np_smem);
    cudaFuncSetAttribute(k_fused,    cudaFuncAttributeMaxDynamicSharedMemorySize, fk_smem);

    k_zero<<<32, 256>>>();
    k_count<<<(E_ + 255) / 256, 256>>>(bi, si, ri);
    k_scan2<<<2, 1024>>>();
    k_scatter<<<(E_ + 255) / 256, 256>>>(bi, si, ri);
    k_nodeproj<<<ROWS_ / 128, 128, np_smem>>>(x, A1w, A1b, A2w, A2b);
    k_fused<<<SEG_, 384, fk_smem>>>(bi, ri, A3w, A4w, A4b, outv);
    k_aggregate<<<SEG_, 256>>>(x, outv, bi, si, outx);
}

// round 6
// speedup vs baseline: 1.0962x; 1.0962x over previous
#include <cuda_runtime.h>
#include <cuda_bf16.h>
#include <cstdint>

#define B_    4
#define N_    1000
#define T_    12
#define D_    64
#define HID_  128
#define EF_   64
#define E_    64000
#define SEG_  (B_*N_)       // 4000
#define ROWS_ (SEG_*T_)     // 48000
#define TD_   (T_*D_)       // 768
#define TH_   (T_*HID_)     // 1536
#define MROWS_ (E_*T_)      // 768000
#define TILE_M 192
#define NTILE_ (MROWS_/TILE_M)   // 4000

// ---------------- device scratch ----------------
__device__ float g_S1[ROWS_ * HID_];
__device__ float g_S2[ROWS_ * HID_];
__device__ int   g_off[2 * (SEG_ + 1)];
__device__ int   g_cur[2 * SEG_];
__device__ int   g_csr_s[E_];
__device__ int   g_csr_r[E_];

// ---------------- mma.sync bf16 (sm_80+ legacy tensor path) ----------------
__device__ __forceinline__ void mma_bf16(float& d0, float& d1, float& d2, float& d3,
                                         uint32_t a0, uint32_t a1, uint32_t a2, uint32_t a3,
                                         uint32_t b0, uint32_t b1) {
    asm("mma.sync.aligned.m16n8k16.row.col.f32.bf16.bf16.f32 "
        "{%0,%1,%2,%3},{%4,%5,%6,%7},{%8,%9},{%0,%1,%2,%3};"
        : "+f"(d0), "+f"(d1), "+f"(d2), "+f"(d3)
        : "r"(a0), "r"(a1), "r"(a2), "r"(a3), "r"(b0), "r"(b1));
}

// split x,y into bf16 hi pair + lo pair (low half = first element)
__device__ __forceinline__ void bf16_split2(float x, float y, uint32_t& hi, uint32_t& lo) {
    __nv_bfloat162 h2 = __float22bfloat162_rn(make_float2(x, y));
    hi = *(uint32_t*)&h2;
    float2 hf = __bfloat1622float2(h2);
    __nv_bfloat162 l2 = __float22bfloat162_rn(make_float2(x - hf.x, y - hf.y));
    lo = *(uint32_t*)&l2;
}

// ---------------- CSR: fused count + scan (single block) ----------------
__global__ void k_countscan(const int* __restrict__ bi, const int* __restrict__ si,
                            const int* __restrict__ ri) {
    __shared__ int cnt[2 * SEG_];
    __shared__ int part[1024];
    int tid = threadIdx.x;
    for (int i = tid; i < 2 * SEG_; i += 1024) cnt[i] = 0;
    __syncthreads();
    for (int e = tid; e < E_; e += 1024) {
        int b = bi[e];
        atomicAdd(&cnt[b * N_ + si[e]], 1);
        atomicAdd(&cnt[SEG_ + b * N_ + ri[e]], 1);
    }
    __syncthreads();
    for (int which = 0; which < 2; which++) {
        int l[4]; int s = 0;
#pragma unroll
        for (int j = 0; j < 4; j++) {
            int idx = tid * 4 + j;
            l[j] = (idx < SEG_) ? cnt[which * SEG_ + idx] : 0;
            s += l[j];
        }
        part[tid] = s;
        __syncthreads();
        for (int o = 1; o < 1024; o <<= 1) {
            int v = part[tid];
            int a = (tid >= o) ? part[tid - o] : 0;
            __syncthreads();
            part[tid] = v + a;
            __syncthreads();
        }
        int run = (tid > 0) ? part[tid - 1] : 0;
        int* off = g_off + which * (SEG_ + 1);
        int* cur = g_cur + which * SEG_;
#pragma unroll
        for (int j = 0; j < 4; j++) {
            int idx = tid * 4 + j;
            if (idx < SEG_) { off[idx] = run; cur[idx] = run; run += l[j]; }
        }
        if (tid == 1023) off[SEG_] = part[1023];
        __syncthreads();
    }
}

__global__ void k_scatter(const int* __restrict__ bi, const int* __restrict__ si,
                          const int* __restrict__ ri) {
    int e = blockIdx.x * blockDim.x + threadIdx.x;
    if (e >= E_) return;
    int b = bi[e];
    int ps = atomicAdd(&g_cur[b * N_ + si[e]], 1);
    g_csr_s[ps] = e;
    int pr = atomicAdd(&g_cur[SEG_ + b * N_ + ri[e]], 1);
    g_csr_r[pr] = e;
}

// ---------------- node projection ----------------
#define NP_SMEM_FLOATS (8192 + 8192 + 512)
__global__ void k_nodeproj(const float* __restrict__ x,
                           const float* __restrict__ A1w, const float* __restrict__ A1b,
                           const float* __restrict__ A2w, const float* __restrict__ A2b) {
    extern __shared__ float shp[];
    float* A1sh = shp;
    float* A2sh = shp + 8192;
    float* xsh  = shp + 16384;
    int tid = threadIdx.x;
    {
        float4* d1 = (float4*)A1sh; const float4* s1 = (const float4*)A1w;
        for (int i = tid; i < 2048; i += 128) d1[i] = s1[i];
        float4* d2 = (float4*)A2sh; const float4* s2 = (const float4*)A2w;
        for (int i = tid; i < 2048; i += 128) d2[i] = s2[i];
    }
    float b12 = A1b[tid] + A2b[tid];
    int rowBase = blockIdx.x * 128;
    for (int p = 0; p < 16; p++) {
        int r0 = rowBase + p * 8;
        __syncthreads();
        for (int i = tid; i < 512; i += 128) xsh[i] = x[(size_t)r0 * 64 + i];
        __syncthreads();
        float a1[8], a2[8];
#pragma unroll
        for (int r = 0; r < 8; r++) { a1[r] = b12; a2[r] = 0.f; }
#pragma unroll 4
        for (int d = 0; d < 64; d++) {
            float w1 = A1sh[d * 128 + tid];
            float w2 = A2sh[d * 128 + tid];
#pragma unroll
            for (int r = 0; r < 8; r++) {
                float xv = xsh[r * 64 + d];
                a1[r] = fmaf(xv, w1, a1[r]);
                a2[r] = fmaf(xv, w2, a2[r]);
            }
        }
#pragma unroll
        for (int r = 0; r < 8; r++) {
            g_S1[(size_t)(r0 + r) * 128 + tid] = a1[r];
            g_S2[(size_t)(r0 + r) * 128 + tid] = a2[r];
        }
    }
}

// ---------------- tensor-core edge kernel (mma.sync bf16 split) ----------------
// SMEM layout (bytes). B fragments stored fragment-linear:
//  index = ((s*8 + nt)*2 + reg)*32 + lane, each entry = packed bf16 pair (u32).
#define SM_B1H  0               // [8s][8nt][2][32] u32 = 16 KB
#define SM_B1L  16384
#define SM_B2H  32768           // [4s][8nt][2][32] u32 = 8 KB
#define SM_B2L  40960
#define SM_BIAS 49152           // 64 floats
#define SM_A1   49664           // per warp 8 KB (hi 4 KB + lo 4 KB), 12 warps
#define SM_A2   (SM_A1 + 12*8192)            // per warp 4 KB (hi 2 KB + lo 2 KB)
#define EM_SMEM (SM_A2 + 12*4096)            // 197120 B total

__global__ void __launch_bounds__(384, 1)
k_edge_mma(const int* __restrict__ bi, const int* __restrict__ si,
           const int* __restrict__ ri,
           const float* __restrict__ A3w, const float* __restrict__ A4w,
           const float* __restrict__ A4b, float* __restrict__ outv) {
    extern __shared__ char smem[];
    int tid = threadIdx.x;
    int w = tid >> 5;
    int l = tid & 31;

    // ---- stage B1 = A3^T, B2 = A4^T as hi/lo bf16 fragment-linear ----
    for (int idx = tid; idx < 4096; idx += 384) {
        int lane = idx & 31, reg = (idx >> 5) & 1, nt = (idx >> 6) & 7, s = idx >> 9;
        int k = s * 16 + reg * 8 + 2 * (lane & 3);
        int n = nt * 8 + (lane >> 2);
        float v0 = A3w[k * 64 + n];
        float v1 = A3w[(k + 1) * 64 + n];
        uint32_t hi, lo;
        bf16_split2(v0, v1, hi, lo);
        *(uint32_t*)(smem + SM_B1H + idx * 4) = hi;
        *(uint32_t*)(smem + SM_B1L + idx * 4) = lo;
    }
    for (int idx = tid; idx < 2048; idx += 384) {
        int lane = idx & 31, reg = (idx >> 5) & 1, nt = (idx >> 6) & 7, s = idx >> 9;
        int k = s * 16 + reg * 8 + 2 * (lane & 3);
        int n = nt * 8 + (lane >> 2);
        float v0 = A4w[k * 64 + n];
        float v1 = A4w[(k + 1) * 64 + n];
        uint32_t hi, lo;
        bf16_split2(v0, v1, hi, lo);
        *(uint32_t*)(smem + SM_B2H + idx * 4) = hi;
        *(uint32_t*)(smem + SM_B2L + idx * 4) = lo;
    }
    if (tid < 64) *(float*)(smem + SM_BIAS + tid * 4) = A4b[tid];
    __syncthreads();

    char* A1h = smem + SM_A1 + w * 8192;
    char* A1l = A1h + 4096;
    char* A2h = smem + SM_A2 + w * 4096;
    char* A2l = A2h + 2048;
    const float* biasSh = (const float*)(smem + SM_BIAS);

    int lr = l >> 1, hf = l & 1;          // build-phase row / k-half
    int rhi = lr >> 3;
    int lanebase = (lr & 7) * 4;
    int lr0 = l >> 2;                      // fragment row (groupID)
    int col0 = 2 * (l & 3);

    for (int tile = blockIdx.x; tile < NTILE_; tile += gridDim.x) {
        __syncwarp();
        // ---- build: gather + relu-diff -> A1 fragments (warp-local) ----
        {
            int g = tile * TILE_M + w * 16 + lr;
            int e = g / 12, tt = g - e * 12;
            int bb = bi[e];
            int ns = bb * N_ + si[e], nr = bb * N_ + ri[e];
            size_t o = (size_t)tt * 128 + hf * 64;
            const float4* p1s = (const float4*)(g_S1 + (size_t)ns * TH_ + o);
            const float4* p2s = (const float4*)(g_S2 + (size_t)ns * TH_ + o);
            const float4* p1r = (const float4*)(g_S1 + (size_t)nr * TH_ + o);
            const float4* p2r = (const float4*)(g_S2 + (size_t)nr * TH_ + o);
#pragma unroll 4
            for (int j = 0; j < 16; j++) {
                float4 a = p1s[j], b4 = p2r[j], c = p1r[j], d = p2s[j];
                float h0 = fmaxf(a.x + b4.x, 0.f) - fmaxf(c.x + d.x, 0.f);
                float h1 = fmaxf(a.y + b4.y, 0.f) - fmaxf(c.y + d.y, 0.f);
                float h2 = fmaxf(a.z + b4.z, 0.f) - fmaxf(c.z + d.z, 0.f);
                float h3 = fmaxf(a.w + b4.w, 0.f) - fmaxf(c.w + d.w, 0.f);
                uint32_t hiA, loA, hiB, loB;
                bf16_split2(h0, h1, hiA, loA);
                bf16_split2(h2, h3, hiB, loB);
                int k0 = hf * 64 + j * 4;
                int s = k0 >> 4, khi = (k0 >> 3) & 1, pidx = (k0 & 7) >> 1;
                int reg = rhi + 2 * khi;
                uint32_t off = (uint32_t)(((s * 4 + reg) * 32 + lanebase + pidx) * 4);
                *(uint2*)(A1h + off) = make_uint2(hiA, hiB);
                *(uint2*)(A1l + off) = make_uint2(loA, loB);
            }
        }
        __syncwarp();

        // ---- GEMM1: [16 x 64] += hdiff[16 x 128] @ A3[128 x 64], 3-term bf16 ----
        float acc[8][4];
#pragma unroll
        for (int nt = 0; nt < 8; nt++)
#pragma unroll
            for (int r = 0; r < 4; r++) acc[nt][r] = 0.f;
#pragma unroll
        for (int s = 0; s < 8; s++) {
            uint32_t ah[4], al[4];
#pragma unroll
            for (int r = 0; r < 4; r++) {
                ah[r] = *(const uint32_t*)(A1h + ((s * 4 + r) * 32 + l) * 4);
                al[r] = *(const uint32_t*)(A1l + ((s * 4 + r) * 32 + l) * 4);
            }
#pragma unroll
            for (int nt = 0; nt < 8; nt++) {
                uint32_t boff = (uint32_t)((((s * 8 + nt) * 2) * 32 + l) * 4);
                uint32_t bh0 = *(const uint32_t*)(smem + SM_B1H + boff);
                uint32_t bh1 = *(const uint32_t*)(smem + SM_B1H + boff + 128);
                uint32_t bl0 = *(const uint32_t*)(smem + SM_B1L + boff);
                uint32_t bl1 = *(const uint32_t*)(smem + SM_B1L + boff + 128);
                mma_bf16(acc[nt][0], acc[nt][1], acc[nt][2], acc[nt][3],
                         ah[0], ah[1], ah[2], ah[3], bh0, bh1);
                mma_bf16(acc[nt][0], acc[nt][1], acc[nt][2], acc[nt][3],
                         al[0], al[1], al[2], al[3], bh0, bh1);
                mma_bf16(acc[nt][0], acc[nt][1], acc[nt][2], acc[nt][3],
                         ah[0], ah[1], ah[2], ah[3], bl0, bl1);
            }
        }

        // ---- epilogue1: relu + split -> A2 fragments (warp-local) ----
#pragma unroll
        for (int nt = 0; nt < 8; nt++) {
            float x0 = fmaxf(acc[nt][0], 0.f), x1 = fmaxf(acc[nt][1], 0.f);
            float x2 = fmaxf(acc[nt][2], 0.f), x3 = fmaxf(acc[nt][3], 0.f);
            uint32_t hi0, lo0, hi1, lo1;
            bf16_split2(x0, x1, hi0, lo0);
            bf16_split2(x2, x3, hi1, lo1);
            int s2 = nt >> 1, khi = nt & 1;
            uint32_t o0 = (uint32_t)(((s2 * 4 + 2 * khi + 0) * 32 + l) * 4);
            uint32_t o1 = (uint32_t)(((s2 * 4 + 2 * khi + 1) * 32 + l) * 4);
            *(uint32_t*)(A2h + o0) = hi0;
            *(uint32_t*)(A2h + o1) = hi1;
            *(uint32_t*)(A2l + o0) = lo0;
            *(uint32_t*)(A2l + o1) = lo1;
        }
        __syncwarp();

        // ---- GEMM2: [16 x 64] += relu(d)[16 x 64] @ A4[64 x 64] ----
        float vac[8][4];
#pragma unroll
        for (int nt = 0; nt < 8; nt++)
#pragma unroll
            for (int r = 0; r < 4; r++) vac[nt][r] = 0.f;
#pragma unroll
        for (int s = 0; s < 4; s++) {
            uint32_t ah[4], al[4];
#pragma unroll
            for (int r = 0; r < 4; r++) {
                ah[r] = *(const uint32_t*)(A2h + ((s * 4 + r) * 32 + l) * 4);
                al[r] = *(const uint32_t*)(A2l + ((s * 4 + r) * 32 + l) * 4);
            }
#pragma unroll
            for (int nt = 0; nt < 8; nt++) {
                uint32_t boff = (uint32_t)((((s * 8 + nt) * 2) * 32 + l) * 4);
                uint32_t bh0 = *(const uint32_t*)(smem + SM_B2H + boff);
                uint32_t bh1 = *(const uint32_t*)(smem + SM_B2H + boff + 128);
                uint32_t bl0 = *(const uint32_t*)(smem + SM_B2L + boff);
                uint32_t bl1 = *(const uint32_t*)(smem + SM_B2L + boff + 128);
                mma_bf16(vac[nt][0], vac[nt][1], vac[nt][2], vac[nt][3],
                         ah[0], ah[1], ah[2], ah[3], bh0, bh1);
                mma_bf16(vac[nt][0], vac[nt][1], vac[nt][2], vac[nt][3],
                         al[0], al[1], al[2], al[3], bh0, bh1);
                mma_bf16(vac[nt][0], vac[nt][1], vac[nt][2], vac[nt][3],
                         ah[0], ah[1], ah[2], ah[3], bl0, bl1);
            }
        }

        // ---- epilogue2: bias + STG ----
        {
            int g0 = tile * TILE_M + w * 16 + lr0;
            int e0 = g0 / 12, t0 = g0 - 12 * e0;
            int g1 = g0 + 8;
            int e1 = g1 / 12, t1 = g1 - 12 * e1;
            float* ob0 = outv + (size_t)e0 * TD_ + t0 * 64;
            float* ob1 = outv + (size_t)e1 * TD_ + t1 * 64;
#pragma unroll
            for (int nt = 0; nt < 8; nt++) {
                int c = nt * 8 + col0;
                float bz0 = biasSh[c], bz1 = biasSh[c + 1];
                *(float2*)(ob0 + c) = make_float2(vac[nt][0] + bz0, vac[nt][1] + bz1);
                *(float2*)(ob1 + c) = make_float2(vac[nt][2] + bz0, vac[nt][3] + bz1);
            }
        }
    }
}

// ---------------- per-sender-segment softmax (in place in outv) ----------------
__global__ void k_softmax(float* __restrict__ v) {
    int seg = blockIdx.x;
    int beg = g_off[seg], end = g_off[seg + 1];
    if (beg == end) return;
    int tid = threadIdx.x;
    int c0 = tid, c1 = tid + 256, c2 = tid + 512;
    float m0 = -1e30f, m1 = -1e30f, m2 = -1e30f;
    for (int i = beg; i < end; i++) {
        const float* vp = v + (size_t)g_csr_s[i] * TD_;
        m0 = fmaxf(m0, vp[c0]); m1 = fmaxf(m1, vp[c1]); m2 = fmaxf(m2, vp[c2]);
    }
    float s0 = 0.f, s1 = 0.f, s2 = 0.f;
    for (int i = beg; i < end; i++) {
        const float* vp = v + (size_t)g_csr_s[i] * TD_;
        s0 += __expf(vp[c0] - m0); s1 += __expf(vp[c1] - m1); s2 += __expf(vp[c2] - m2);
    }
    float r0 = 1.f / (s0 + 1e-12f), r1 = 1.f / (s1 + 1e-12f), r2 = 1.f / (s2 + 1e-12f);
    for (int i = beg; i < end; i++) {
        float* vp = v + (size_t)g_csr_s[i] * TD_;
        vp[c0] = __expf(vp[c0] - m0) * r0;
        vp[c1] = __expf(vp[c1] - m1) * r1;
        vp[c2] = __expf(vp[c2] - m2) * r2;
    }
}

// ---------------- per-receiver aggregation + x update ----------------
__global__ void k_aggregate(const float* __restrict__ x, const float* __restrict__ v,
                            const int* __restrict__ bi, const int* __restrict__ si,
                            float* __restrict__ outx) {
    int seg = blockIdx.x;
    int tid = threadIdx.x;
    int beg = g_off[(SEG_ + 1) + seg], end = g_off[(SEG_ + 1) + seg + 1];
    int c0 = tid, c1 = tid + 256, c2 = tid + 512;
    float a0 = 0.f, a1 = 0.f, a2 = 0.f;
    for (int i = beg; i < end; i++) {
        int e = g_csr_r[i];
        int ns = bi[e] * N_ + si[e];
        const float* vp = v + (size_t)e * TD_;
        const float* xs = x + (size_t)ns * TD_;
        a0 = fmaf(vp[c0], xs[c0], a0);
        a1 = fmaf(vp[c1], xs[c1], a1);
        a2 = fmaf(vp[c2], xs[c2], a2);
    }
    const float* xr = x + (size_t)seg * TD_;
    float* o = outx + (size_t)seg * TD_;
    o[c0] = xr[c0] + 0.1f * (a0 - xr[c0]);
    o[c1] = xr[c1] + 0.1f * (a1 - xr[c1]);
    o[c2] = xr[c2] + 0.1f * (a2 - xr[c2]);
}

// ---------------- launch ----------------
extern "C" void kernel_launch(void* const* d_in, const int* in_sizes, int n_in,
                              void* d_out, int out_size) {
    const float* x   = (const float*)d_in[0];
    const int*   bi  = (const int*)d_in[1];
    const int*   si  = (const int*)d_in[2];
    const int*   ri  = (const int*)d_in[3];
    const float* A1w = (const float*)d_in[4];
    const float* A1b = (const float*)d_in[5];
    const float* A2w = (const float*)d_in[6];
    const float* A2b = (const float*)d_in[7];
    const float* A3w = (const float*)d_in[8];
    // d_in[9] = A3_b: cancels in z_ij - z_ji
    const float* A4w = (const float*)d_in[10];
    const float* A4b = (const float*)d_in[11];

    float* outx = (float*)d_out;
    float* outv = outx + (size_t)ROWS_ * D_;

    const int np_smem = NP_SMEM_FLOATS * 4;
    cudaFuncSetAttribute(k_nodeproj, cudaFuncAttributeMaxDynamicSharedMemorySize, np_smem);
    cudaFuncSetAttribute(k_edge_mma, cudaFuncAttributeMaxDynamicSharedMemorySize, EM_SMEM);

    k_countscan<<<1, 1024>>>(bi, si, ri);
    k_scatter<<<(E_ + 255) / 256, 256>>>(bi, si, ri);
    k_nodeproj<<<ROWS_ / 128, 128, np_smem>>>(x, A1w, A1b, A2w, A2b);
    k_edge_mma<<<148, 384, EM_SMEM>>>(bi, si, ri, A3w, A4w, A4b, outv);
    k_softmax<<<SEG_, 256>>>(outv);
    k_aggregate<<<SEG_, 256>>>(x, outv, bi, si, outx);
}

// round 7
// speedup vs baseline: 1.6845x; 1.5367x over previous
#include <cuda_runtime.h>
#include <cuda_bf16.h>
#include <cstdint>

#define B_    4
#define N_    1000
#define T_    12
#define D_    64
#define HID_  128
#define EF_   64
#define E_    64000
#define SEG_  (B_*N_)       // 4000
#define ROWS_ (SEG_*T_)     // 48000
#define TD_   (T_*D_)       // 768
#define TH_   (T_*HID_)     // 1536
#define MROWS_ (E_*T_)      // 768000
#define TILE_M 192
#define NTILE_ (MROWS_/TILE_M)   // 4000

// ---------------- device scratch ----------------
__device__ float g_S1[ROWS_ * HID_];
__device__ float g_S2[ROWS_ * HID_];
__device__ int   g_off[2 * (SEG_ + 1)];
__device__ int   g_cur[2 * SEG_];
__device__ int   g_csr_s[E_];
__device__ int   g_csr_r[E_];

// ---------------- mma.sync bf16 (sm_80+ legacy tensor path) ----------------
__device__ __forceinline__ void mma_bf16(float& d0, float& d1, float& d2, float& d3,
                                         uint32_t a0, uint32_t a1, uint32_t a2, uint32_t a3,
                                         uint32_t b0, uint32_t b1) {
    asm("mma.sync.aligned.m16n8k16.row.col.f32.bf16.bf16.f32 "
        "{%0,%1,%2,%3},{%4,%5,%6,%7},{%8,%9},{%0,%1,%2,%3};"
        : "+f"(d0), "+f"(d1), "+f"(d2), "+f"(d3)
        : "r"(a0), "r"(a1), "r"(a2), "r"(a3), "r"(b0), "r"(b1));
}

// split x,y into bf16 hi pair + lo pair (low half = first element)
__device__ __forceinline__ void bf16_split2(float x, float y, uint32_t& hi, uint32_t& lo) {
    __nv_bfloat162 h2 = __float22bfloat162_rn(make_float2(x, y));
    hi = *(uint32_t*)&h2;
    float2 hf = __bfloat1622float2(h2);
    __nv_bfloat162 l2 = __float22bfloat162_rn(make_float2(x - hf.x, y - hf.y));
    lo = *(uint32_t*)&l2;
}

// ---------------- CSR: fused count + scan (single block) ----------------
__global__ void k_countscan(const int* __restrict__ bi, const int* __restrict__ si,
                            const int* __restrict__ ri) {
    __shared__ int cnt[2 * SEG_];
    __shared__ int part[1024];
    int tid = threadIdx.x;
    for (int i = tid; i < 2 * SEG_; i += 1024) cnt[i] = 0;
    __syncthreads();
    for (int e = tid; e < E_; e += 1024) {
        int b = bi[e];
        atomicAdd(&cnt[b * N_ + si[e]], 1);
        atomicAdd(&cnt[SEG_ + b * N_ + ri[e]], 1);
    }
    __syncthreads();
    for (int which = 0; which < 2; which++) {
        int l[4]; int s = 0;
#pragma unroll
        for (int j = 0; j < 4; j++) {
            int idx = tid * 4 + j;
            l[j] = (idx < SEG_) ? cnt[which * SEG_ + idx] : 0;
            s += l[j];
        }
        part[tid] = s;
        __syncthreads();
        for (int o = 1; o < 1024; o <<= 1) {
            int v = part[tid];
            int a = (tid >= o) ? part[tid - o] : 0;
            __syncthreads();
            part[tid] = v + a;
            __syncthreads();
        }
        int run = (tid > 0) ? part[tid - 1] : 0;
        int* off = g_off + which * (SEG_ + 1);
        int* cur = g_cur + which * SEG_;
#pragma unroll
        for (int j = 0; j < 4; j++) {
            int idx = tid * 4 + j;
            if (idx < SEG_) { off[idx] = run; cur[idx] = run; run += l[j]; }
        }
        if (tid == 1023) off[SEG_] = part[1023];
        __syncthreads();
    }
}

__global__ void k_scatter(const int* __restrict__ bi, const int* __restrict__ si,
                          const int* __restrict__ ri) {
    int e = blockIdx.x * blockDim.x + threadIdx.x;
    if (e >= E_) return;
    int b = bi[e];
    int ps = atomicAdd(&g_cur[b * N_ + si[e]], 1);
    g_csr_s[ps] = e;
    int pr = atomicAdd(&g_cur[SEG_ + b * N_ + ri[e]], 1);
    g_csr_r[pr] = e;
}

// ---------------- node projection ----------------
#define NP_SMEM_FLOATS (8192 + 8192 + 512)
__global__ void k_nodeproj(const float* __restrict__ x,
                           const float* __restrict__ A1w, const float* __restrict__ A1b,
                           const float* __restrict__ A2w, const float* __restrict__ A2b) {
    extern __shared__ float shp[];
    float* A1sh = shp;
    float* A2sh = shp + 8192;
    float* xsh  = shp + 16384;
    int tid = threadIdx.x;
    {
        float4* d1 = (float4*)A1sh; const float4* s1 = (const float4*)A1w;
        for (int i = tid; i < 2048; i += 128) d1[i] = s1[i];
        float4* d2 = (float4*)A2sh; const float4* s2 = (const float4*)A2w;
        for (int i = tid; i < 2048; i += 128) d2[i] = s2[i];
    }
    float b12 = A1b[tid] + A2b[tid];
    int rowBase = blockIdx.x * 128;
    for (int p = 0; p < 16; p++) {
        int r0 = rowBase + p * 8;
        __syncthreads();
        for (int i = tid; i < 512; i += 128) xsh[i] = x[(size_t)r0 * 64 + i];
        __syncthreads();
        float a1[8], a2[8];
#pragma unroll
        for (int r = 0; r < 8; r++) { a1[r] = b12; a2[r] = 0.f; }
#pragma unroll 4
        for (int d = 0; d < 64; d++) {
            float w1 = A1sh[d * 128 + tid];
            float w2 = A2sh[d * 128 + tid];
#pragma unroll
            for (int r = 0; r < 8; r++) {
                float xv = xsh[r * 64 + d];
                a1[r] = fmaf(xv, w1, a1[r]);
                a2[r] = fmaf(xv, w2, a2[r]);
            }
        }
#pragma unroll
        for (int r = 0; r < 8; r++) {
            g_S1[(size_t)(r0 + r) * 128 + tid] = a1[r];
            g_S2[(size_t)(r0 + r) * 128 + tid] = a2[r];
        }
    }
}

// ---------------- tensor-core edge kernel (mma.sync bf16 split) ----------------
// B fragments stored fragment-linear: index = ((s*8 + nt)*2 + reg)*32 + lane.
// A fragments stored fragment-linear with XOR swizzle: word = (s*4+reg)*32 + (lane ^ 4s).
#define SM_B1H  0               // [8s][8nt][2][32] u32 = 16 KB
#define SM_B1L  16384
#define SM_B2H  32768           // [4s][8nt][2][32] u32 = 8 KB
#define SM_B2L  40960
#define SM_BIAS 49152           // 64 floats
#define SM_A1   49664           // per warp 8 KB (hi 4 KB + lo 4 KB), 12 warps
#define SM_A2   (SM_A1 + 12*8192)            // per warp 4 KB (hi 2 KB + lo 2 KB)
#define EM_SMEM (SM_A2 + 12*4096)            // 197120 B total

__global__ void __launch_bounds__(384, 1)
k_edge_mma(const int* __restrict__ bi, const int* __restrict__ si,
           const int* __restrict__ ri,
           const float* __restrict__ A3w, const float* __restrict__ A4w,
           const float* __restrict__ A4b, float* __restrict__ outv) {
    extern __shared__ char smem[];
    int tid = threadIdx.x;
    int w = tid >> 5;
    int l = tid & 31;

    // ---- stage B1 = A3^T, B2 = A4^T as hi/lo bf16 fragment-linear ----
    for (int idx = tid; idx < 4096; idx += 384) {
        int lane = idx & 31, reg = (idx >> 5) & 1, nt = (idx >> 6) & 7, s = idx >> 9;
        int k = s * 16 + reg * 8 + 2 * (lane & 3);
        int n = nt * 8 + (lane >> 2);
        float v0 = A3w[k * 64 + n];
        float v1 = A3w[(k + 1) * 64 + n];
        uint32_t hi, lo;
        bf16_split2(v0, v1, hi, lo);
        *(uint32_t*)(smem + SM_B1H + idx * 4) = hi;
        *(uint32_t*)(smem + SM_B1L + idx * 4) = lo;
    }
    for (int idx = tid; idx < 2048; idx += 384) {
        int lane = idx & 31, reg = (idx >> 5) & 1, nt = (idx >> 6) & 7, s = idx >> 9;
        int k = s * 16 + reg * 8 + 2 * (lane & 3);
        int n = nt * 8 + (lane >> 2);
        float v0 = A4w[k * 64 + n];
        float v1 = A4w[(k + 1) * 64 + n];
        uint32_t hi, lo;
        bf16_split2(v0, v1, hi, lo);
        *(uint32_t*)(smem + SM_B2H + idx * 4) = hi;
        *(uint32_t*)(smem + SM_B2L + idx * 4) = lo;
    }
    if (tid < 64) *(float*)(smem + SM_BIAS + tid * 4) = A4b[tid];
    __syncthreads();

    char* A1h = smem + SM_A1 + w * 8192;
    char* A1l = A1h + 4096;
    char* A2h = smem + SM_A2 + w * 4096;
    char* A2l = A2h + 2048;
    const float* biasSh = (const float*)(smem + SM_BIAS);

    // build-phase constants: lane l owns cols 4l..4l+3 of each row
    int bs   = l >> 2;            // k-block s of col 4l
    int bkhi = (l >> 1) & 1;      // (4l>>3)&1
    int blpar= l & 1;
    int lr0 = l >> 2;             // fragment row (groupID)
    int col0 = 2 * (l & 3);

    for (int tile = blockIdx.x; tile < NTILE_; tile += gridDim.x) {
        __syncwarp();
        // ---- build: coalesced gather + relu-diff -> swizzled A1 fragments ----
#pragma unroll 2
        for (int j = 0; j < 16; j++) {
            int g = tile * TILE_M + w * 16 + j;
            int e = g / 12, tt = g - e * 12;
            int bb = bi[e];
            int ns = bb * N_ + si[e], nr = bb * N_ + ri[e];
            size_t o = (size_t)tt * 128 + 4 * l;
            float4 a  = *(const float4*)(g_S1 + (size_t)ns * TH_ + o);
            float4 d  = *(const float4*)(g_S2 + (size_t)ns * TH_ + o);
            float4 c  = *(const float4*)(g_S1 + (size_t)nr * TH_ + o);
            float4 b4 = *(const float4*)(g_S2 + (size_t)nr * TH_ + o);
            float h0 = fmaxf(a.x + b4.x, 0.f) - fmaxf(c.x + d.x, 0.f);
            float h1 = fmaxf(a.y + b4.y, 0.f) - fmaxf(c.y + d.y, 0.f);
            float h2 = fmaxf(a.z + b4.z, 0.f) - fmaxf(c.z + d.z, 0.f);
            float h3 = fmaxf(a.w + b4.w, 0.f) - fmaxf(c.w + d.w, 0.f);
            uint32_t hiA, loA, hiB, loB;
            bf16_split2(h0, h1, hiA, loA);
            bf16_split2(h2, h3, hiB, loB);
            int reg = (j >> 3) + 2 * bkhi;
            int lf0 = (j & 7) * 4 + 2 * blpar;          // even
            uint32_t word = (uint32_t)((bs * 4 + reg) * 32 + (lf0 ^ (4 * bs)));
            *(uint2*)(A1h + word * 4) = make_uint2(hiA, hiB);
            *(uint2*)(A1l + word * 4) = make_uint2(loA, loB);
        }
        __syncwarp();

        // ---- GEMM1: [16 x 64] += hdiff[16 x 128] @ A3[128 x 64], 3-term bf16 ----
        float acc[8][4];
#pragma unroll
        for (int nt = 0; nt < 8; nt++)
#pragma unroll
            for (int r = 0; r < 4; r++) acc[nt][r] = 0.f;
#pragma unroll
        for (int s = 0; s < 8; s++) {
            int lsw = l ^ (4 * s);
            uint32_t ah[4], al[4];
#pragma unroll
            for (int r = 0; r < 4; r++) {
                ah[r] = *(const uint32_t*)(A1h + ((s * 4 + r) * 32 + lsw) * 4);
                al[r] = *(const uint32_t*)(A1l + ((s * 4 + r) * 32 + lsw) * 4);
            }
#pragma unroll
            for (int nt = 0; nt < 8; nt++) {
                uint32_t boff = (uint32_t)((((s * 8 + nt) * 2) * 32 + l) * 4);
                uint32_t bh0 = *(const uint32_t*)(smem + SM_B1H + boff);
                uint32_t bh1 = *(const uint32_t*)(smem + SM_B1H + boff + 128);
                uint32_t bl0 = *(const uint32_t*)(smem + SM_B1L + boff);
                uint32_t bl1 = *(const uint32_t*)(smem + SM_B1L + boff + 128);
                mma_bf16(acc[nt][0], acc[nt][1], acc[nt][2], acc[nt][3],
                         ah[0], ah[1], ah[2], ah[3], bh0, bh1);
                mma_bf16(acc[nt][0], acc[nt][1], acc[nt][2], acc[nt][3],
                         al[0], al[1], al[2], al[3], bh0, bh1);
                mma_bf16(acc[nt][0], acc[nt][1], acc[nt][2], acc[nt][3],
                         ah[0], ah[1], ah[2], ah[3], bl0, bl1);
            }
        }

        // ---- epilogue1: relu + split -> swizzled A2 fragments (lf == lane) ----
#pragma unroll
        for (int nt = 0; nt < 8; nt++) {
            float x0 = fmaxf(acc[nt][0], 0.f), x1 = fmaxf(acc[nt][1], 0.f);
            float x2 = fmaxf(acc[nt][2], 0.f), x3 = fmaxf(acc[nt][3], 0.f);
            uint32_t hi0, lo0, hi1, lo1;
            bf16_split2(x0, x1, hi0, lo0);    // rows l>>2     -> rhi=0
            bf16_split2(x2, x3, hi1, lo1);    // rows l>>2 + 8 -> rhi=1
            int s2 = nt >> 1, khi = nt & 1;
            int lsw = l ^ (4 * s2);
            uint32_t o0 = (uint32_t)(((s2 * 4 + 2 * khi + 0) * 32 + lsw) * 4);
            uint32_t o1 = (uint32_t)(((s2 * 4 + 2 * khi + 1) * 32 + lsw) * 4);
            *(uint32_t*)(A2h + o0) = hi0;
            *(uint32_t*)(A2h + o1) = hi1;
            *(uint32_t*)(A2l + o0) = lo0;
            *(uint32_t*)(A2l + o1) = lo1;
        }
        __syncwarp();

        // ---- GEMM2: [16 x 64] += relu(d)[16 x 64] @ A4[64 x 64] ----
        float vac[8][4];
#pragma unroll
        for (int nt = 0; nt < 8; nt++)
#pragma unroll
            for (int r = 0; r < 4; r++) vac[nt][r] = 0.f;
#pragma unroll
        for (int s = 0; s < 4; s++) {
            int lsw = l ^ (4 * s);
            uint32_t ah[4], al[4];
#pragma unroll
            for (int r = 0; r < 4; r++) {
                ah[r] = *(const uint32_t*)(A2h + ((s * 4 + r) * 32 + lsw) * 4);
                al[r] = *(const uint32_t*)(A2l + ((s * 4 + r) * 32 + lsw) * 4);
            }
#pragma unroll
            for (int nt = 0; nt < 8; nt++) {
                uint32_t boff = (uint32_t)((((s * 8 + nt) * 2) * 32 + l) * 4);
                uint32_t bh0 = *(const uint32_t*)(smem + SM_B2H + boff);
                uint32_t bh1 = *(const uint32_t*)(smem + SM_B2H + boff + 128);
                uint32_t bl0 = *(const uint32_t*)(smem + SM_B2L + boff);
                uint32_t bl1 = *(const uint32_t*)(smem + SM_B2L + boff + 128);
                mma_bf16(vac[nt][0], vac[nt][1], vac[nt][2], vac[nt][3],
                         ah[0], ah[1], ah[2], ah[3], bh0, bh1);
                mma_bf16(vac[nt][0], vac[nt][1], vac[nt][2], vac[nt][3],
                         al[0], al[1], al[2], al[3], bh0, bh1);
                mma_bf16(vac[nt][0], vac[nt][1], vac[nt][2], vac[nt][3],
                         ah[0], ah[1], ah[2], ah[3], bl0, bl1);
            }
        }

        // ---- epilogue2: bias + STG ----
        {
            int g0 = tile * TILE_M + w * 16 + lr0;
            int e0 = g0 / 12, t0 = g0 - 12 * e0;
            int g1 = g0 + 8;
            int e1 = g1 / 12, t1 = g1 - 12 * e1;
            float* ob0 = outv + (size_t)e0 * TD_ + t0 * 64;
            float* ob1 = outv + (size_t)e1 * TD_ + t1 * 64;
#pragma unroll
            for (int nt = 0; nt < 8; nt++) {
                int c = nt * 8 + col0;
                float bz0 = biasSh[c], bz1 = biasSh[c + 1];
                *(float2*)(ob0 + c) = make_float2(vac[nt][0] + bz0, vac[nt][1] + bz1);
                *(float2*)(ob1 + c) = make_float2(vac[nt][2] + bz0, vac[nt][3] + bz1);
            }
        }
    }
}

// ---------------- per-sender-segment softmax (in place in outv) ----------------
__global__ void k_softmax(float* __restrict__ v) {
    int seg = blockIdx.x;
    int beg = g_off[seg], end = g_off[seg + 1];
    if (beg == end) return;
    int tid = threadIdx.x;
    int c0 = tid, c1 = tid + 256, c2 = tid + 512;
    float m0 = -1e30f, m1 = -1e30f, m2 = -1e30f;
    for (int i = beg; i < end; i++) {
        const float* vp = v + (size_t)g_csr_s[i] * TD_;
        m0 = fmaxf(m0, vp[c0]); m1 = fmaxf(m1, vp[c1]); m2 = fmaxf(m2, vp[c2]);
    }
    float s0 = 0.f, s1 = 0.f, s2 = 0.f;
    for (int i = beg; i < end; i++) {
        const float* vp = v + (size_t)g_csr_s[i] * TD_;
        s0 += __expf(vp[c0] - m0); s1 += __expf(vp[c1] - m1); s2 += __expf(vp[c2] - m2);
    }
    float r0 = 1.f / (s0 + 1e-12f), r1 = 1.f / (s1 + 1e-12f), r2 = 1.f / (s2 + 1e-12f);
    for (int i = beg; i < end; i++) {
        float* vp = v + (size_t)g_csr_s[i] * TD_;
        vp[c0] = __expf(vp[c0] - m0) * r0;
        vp[c1] = __expf(vp[c1] - m1) * r1;
        vp[c2] = __expf(vp[c2] - m2) * r2;
    }
}

// ---------------- per-receiver aggregation + x update ----------------
__global__ void k_aggregate(const float* __restrict__ x, const float* __restrict__ v,
                            const int* __restrict__ bi, const int* __restrict__ si,
                            float* __restrict__ outx) {
    int seg = blockIdx.x;
    int tid = threadIdx.x;
    int beg = g_off[(SEG_ + 1) + seg], end = g_off[(SEG_ + 1) + seg + 1];
    int c0 = tid, c1 = tid + 256, c2 = tid + 512;
    float a0 = 0.f, a1 = 0.f, a2 = 0.f;
    for (int i = beg; i < end; i++) {
        int e = g_csr_r[i];
        int ns = bi[e] * N_ + si[e];
        const float* vp = v + (size_t)e * TD_;
        const float* xs = x + (size_t)ns * TD_;
        a0 = fmaf(vp[c0], xs[c0], a0);
        a1 = fmaf(vp[c1], xs[c1], a1);
        a2 = fmaf(vp[c2], xs[c2], a2);
    }
    const float* xr = x + (size_t)seg * TD_;
    float* o = outx + (size_t)seg * TD_;
    o[c0] = xr[c0] + 0.1f * (a0 - xr[c0]);
    o[c1] = xr[c1] + 0.1f * (a1 - xr[c1]);
    o[c2] = xr[c2] + 0.1f * (a2 - xr[c2]);
}

// ---------------- launch ----------------
extern "C" void kernel_launch(void* const* d_in, const int* in_sizes, int n_in,
                              void* d_out, int out_size) {
    const float* x   = (const float*)d_in[0];
    const int*   bi  = (const int*)d_in[1];
    const int*   si  = (const int*)d_in[2];
    const int*   ri  = (const int*)d_in[3];
    const float* A1w = (const float*)d_in[4];
    const float* A1b = (const float*)d_in[5];
    const float* A2w = (const float*)d_in[6];
    const float* A2b = (const float*)d_in[7];
    const float* A3w = (const float*)d_in[8];
    // d_in[9] = A3_b: cancels in z_ij - z_ji
    const float* A4w = (const float*)d_in[10];
    const float* A4b = (const float*)d_in[11];

    float* outx = (float*)d_out;
    float* outv = outx + (size_t)ROWS_ * D_;

    const int np_smem = NP_SMEM_FLOATS * 4;
    cudaFuncSetAttribute(k_nodeproj, cudaFuncAttributeMaxDynamicSharedMemorySize, np_smem);
    cudaFuncSetAttribute(k_edge_mma, cudaFuncAttributeMaxDynamicSharedMemorySize, EM_SMEM);

    k_countscan<<<1, 1024>>>(bi, si, ri);
    k_scatter<<<(E_ + 255) / 256, 256>>>(bi, si, ri);
    k_nodeproj<<<ROWS_ / 128, 128, np_smem>>>(x, A1w, A1b, A2w, A2b);
    k_edge_mma<<<148, 384, EM_SMEM>>>(bi, si, ri, A3w, A4w, A4b, outv);
    k_softmax<<<SEG_, 256>>>(outv);
    k_aggregate<<<SEG_, 256>>>(x, outv, bi, si, outx);
}

// round 8
// speedup vs baseline: 1.7234x; 1.0231x over previous
#include <cuda_runtime.h>
#include <cuda_bf16.h>
#include <cstdint>

#define B_    4
#define N_    1000
#define T_    12
#define D_    64
#define HID_  128
#define EF_   64
#define E_    64000
#define SEG_  (B_*N_)       // 4000
#define ROWS_ (SEG_*T_)     // 48000
#define TD_   (T_*D_)       // 768
#define TH_   (T_*HID_)     // 1536
#define MROWS_ (E_*T_)      // 768000
#define TILE_M 128
#define NTILE_ (MROWS_/TILE_M)   // 6000

// ---------------- device scratch ----------------
__device__ float g_S1[ROWS_ * HID_];
__device__ float g_S2[ROWS_ * HID_];
__device__ int   g_off[2 * (SEG_ + 1)];
__device__ int   g_cur[2 * SEG_];
__device__ int   g_csr_s[E_];
__device__ int   g_csr_r[E_];

// ---------------- mma.sync bf16 (sm_80+ legacy tensor path) ----------------
__device__ __forceinline__ void mma_bf16(float& d0, float& d1, float& d2, float& d3,
                                         uint32_t a0, uint32_t a1, uint32_t a2, uint32_t a3,
                                         uint32_t b0, uint32_t b1) {
    asm("mma.sync.aligned.m16n8k16.row.col.f32.bf16.bf16.f32 "
        "{%0,%1,%2,%3},{%4,%5,%6,%7},{%8,%9},{%0,%1,%2,%3};"
        : "+f"(d0), "+f"(d1), "+f"(d2), "+f"(d3)
        : "r"(a0), "r"(a1), "r"(a2), "r"(a3), "r"(b0), "r"(b1));
}

// split x,y into bf16 hi pair + lo pair (low half = first element)
__device__ __forceinline__ void bf16_split2(float x, float y, uint32_t& hi, uint32_t& lo) {
    __nv_bfloat162 h2 = __float22bfloat162_rn(make_float2(x, y));
    hi = *(uint32_t*)&h2;
    float2 hf = __bfloat1622float2(h2);
    __nv_bfloat162 l2 = __float22bfloat162_rn(make_float2(x - hf.x, y - hf.y));
    lo = *(uint32_t*)&l2;
}

// ---------------- CSR: fused count + scan (single block) ----------------
__global__ void k_countscan(const int* __restrict__ bi, const int* __restrict__ si,
                            const int* __restrict__ ri) {
    __shared__ int cnt[2 * SEG_];
    __shared__ int part[1024];
    int tid = threadIdx.x;
    for (int i = tid; i < 2 * SEG_; i += 1024) cnt[i] = 0;
    __syncthreads();
    for (int e = tid; e < E_; e += 1024) {
        int b = bi[e];
        atomicAdd(&cnt[b * N_ + si[e]], 1);
        atomicAdd(&cnt[SEG_ + b * N_ + ri[e]], 1);
    }
    __syncthreads();
    for (int which = 0; which < 2; which++) {
        int l[4]; int s = 0;
#pragma unroll
        for (int j = 0; j < 4; j++) {
            int idx = tid * 4 + j;
            l[j] = (idx < SEG_) ? cnt[which * SEG_ + idx] : 0;
            s += l[j];
        }
        part[tid] = s;
        __syncthreads();
        for (int o = 1; o < 1024; o <<= 1) {
            int v = part[tid];
            int a = (tid >= o) ? part[tid - o] : 0;
            __syncthreads();
            part[tid] = v + a;
            __syncthreads();
        }
        int run = (tid > 0) ? part[tid - 1] : 0;
        int* off = g_off + which * (SEG_ + 1);
        int* cur = g_cur + which * SEG_;
#pragma unroll
        for (int j = 0; j < 4; j++) {
            int idx = tid * 4 + j;
            if (idx < SEG_) { off[idx] = run; cur[idx] = run; run += l[j]; }
        }
        if (tid == 1023) off[SEG_] = part[1023];
        __syncthreads();
    }
}

__global__ void k_scatter(const int* __restrict__ bi, const int* __restrict__ si,
                          const int* __restrict__ ri) {
    int e = blockIdx.x * blockDim.x + threadIdx.x;
    if (e >= E_) return;
    int b = bi[e];
    int ps = atomicAdd(&g_cur[b * N_ + si[e]], 1);
    g_csr_s[ps] = e;
    int pr = atomicAdd(&g_cur[SEG_ + b * N_ + ri[e]], 1);
    g_csr_r[pr] = e;
}

// ---------------- node projection ----------------
#define NP_SMEM_FLOATS (8192 + 8192 + 512)
__global__ void k_nodeproj(const float* __restrict__ x,
                           const float* __restrict__ A1w, const float* __restrict__ A1b,
                           const float* __restrict__ A2w, const float* __restrict__ A2b) {
    extern __shared__ float shp[];
    float* A1sh = shp;
    float* A2sh = shp + 8192;
    float* xsh  = shp + 16384;
    int tid = threadIdx.x;
    {
        float4* d1 = (float4*)A1sh; const float4* s1 = (const float4*)A1w;
        for (int i = tid; i < 2048; i += 128) d1[i] = s1[i];
        float4* d2 = (float4*)A2sh; const float4* s2 = (const float4*)A2w;
        for (int i = tid; i < 2048; i += 128) d2[i] = s2[i];
    }
    float b12 = A1b[tid] + A2b[tid];
    int rowBase = blockIdx.x * 128;
    for (int p = 0; p < 16; p++) {
        int r0 = rowBase + p * 8;
        __syncthreads();
        for (int i = tid; i < 512; i += 128) xsh[i] = x[(size_t)r0 * 64 + i];
        __syncthreads();
        float a1[8], a2[8];
#pragma unroll
        for (int r = 0; r < 8; r++) { a1[r] = b12; a2[r] = 0.f; }
#pragma unroll 4
        for (int d = 0; d < 64; d++) {
            float w1 = A1sh[d * 128 + tid];
            float w2 = A2sh[d * 128 + tid];
#pragma unroll
            for (int r = 0; r < 8; r++) {
                float xv = xsh[r * 64 + d];
                a1[r] = fmaf(xv, w1, a1[r]);
                a2[r] = fmaf(xv, w2, a2[r]);
            }
        }
#pragma unroll
        for (int r = 0; r < 8; r++) {
            g_S1[(size_t)(r0 + r) * 128 + tid] = a1[r];
            g_S2[(size_t)(r0 + r) * 128 + tid] = a2[r];
        }
    }
}

// ---------------- tensor-core edge kernel (mma.sync bf16 split) ----------------
// 256 threads = 8 warps, TILE_M=128, A2 overlays A1 slot -> 114.9 KB -> 2 blocks/SM.
// B fragments fragment-linear: index = ((s*8 + nt)*2 + reg)*32 + lane.
// A fragments fragment-linear with XOR swizzle: word = (s*4+reg)*32 + (lane ^ 4s).
#define SM_B1H  0               // [8s][8nt][2][32] u32 = 16 KB
#define SM_B1L  16384
#define SM_B2H  32768           // [4s][8nt][2][32] u32 = 8 KB
#define SM_B2L  40960
#define SM_BIAS 49152           // 64 floats
#define SM_A1   49408           // per warp 8 KB (hi 4 KB + lo 4 KB), 8 warps
#define EM_SMEM (SM_A1 + 8*8192)             // 114,944 B total

__global__ void __launch_bounds__(256)
k_edge_mma(const int* __restrict__ bi, const int* __restrict__ si,
           const int* __restrict__ ri,
           const float* __restrict__ A3w, const float* __restrict__ A4w,
           const float* __restrict__ A4b, float* __restrict__ outv) {
    extern __shared__ char smem[];
    int tid = threadIdx.x;
    int w = tid >> 5;
    int l = tid & 31;

    // ---- stage B1 = A3^T, B2 = A4^T as hi/lo bf16 fragment-linear ----
    for (int idx = tid; idx < 4096; idx += 256) {
        int lane = idx & 31, reg = (idx >> 5) & 1, nt = (idx >> 6) & 7, s = idx >> 9;
        int k = s * 16 + reg * 8 + 2 * (lane & 3);
        int n = nt * 8 + (lane >> 2);
        float v0 = A3w[k * 64 + n];
        float v1 = A3w[(k + 1) * 64 + n];
        uint32_t hi, lo;
        bf16_split2(v0, v1, hi, lo);
        *(uint32_t*)(smem + SM_B1H + idx * 4) = hi;
        *(uint32_t*)(smem + SM_B1L + idx * 4) = lo;
    }
    for (int idx = tid; idx < 2048; idx += 256) {
        int lane = idx & 31, reg = (idx >> 5) & 1, nt = (idx >> 6) & 7, s = idx >> 9;
        int k = s * 16 + reg * 8 + 2 * (lane & 3);
        int n = nt * 8 + (lane >> 2);
        float v0 = A4w[k * 64 + n];
        float v1 = A4w[(k + 1) * 64 + n];
        uint32_t hi, lo;
        bf16_split2(v0, v1, hi, lo);
        *(uint32_t*)(smem + SM_B2H + idx * 4) = hi;
        *(uint32_t*)(smem + SM_B2L + idx * 4) = lo;
    }
    if (tid < 64) *(float*)(smem + SM_BIAS + tid * 4) = A4b[tid];
    __syncthreads();

    char* A1h = smem + SM_A1 + w * 8192;
    char* A1l = A1h + 4096;
    char* A2h = A1h;              // overlay: A1 dead after GEMM1
    char* A2l = A1l;
    const float* biasSh = (const float*)(smem + SM_BIAS);

    // build-phase constants: lane l owns cols 4l..4l+3 of each row
    int bs   = l >> 2;            // k-block s of col 4l
    int bkhi = (l >> 1) & 1;      // (4l>>3)&1
    int blpar= l & 1;
    int lr0 = l >> 2;             // fragment row (groupID)
    int col0 = 2 * (l & 3);

    for (int tile = blockIdx.x; tile < NTILE_; tile += gridDim.x) {
        __syncwarp();
        // ---- build: coalesced gather + relu-diff -> swizzled A1 fragments ----
#pragma unroll 2
        for (int j = 0; j < 16; j++) {
            int g = tile * TILE_M + w * 16 + j;
            int e = g / 12, tt = g - e * 12;
            int bb = bi[e];
            int ns = bb * N_ + si[e], nr = bb * N_ + ri[e];
            size_t o = (size_t)tt * 128 + 4 * l;
            float4 a  = *(const float4*)(g_S1 + (size_t)ns * TH_ + o);
            float4 d  = *(const float4*)(g_S2 + (size_t)ns * TH_ + o);
            float4 c  = *(const float4*)(g_S1 + (size_t)nr * TH_ + o);
            float4 b4 = *(const float4*)(g_S2 + (size_t)nr * TH_ + o);
            float h0 = fmaxf(a.x + b4.x, 0.f) - fmaxf(c.x + d.x, 0.f);
            float h1 = fmaxf(a.y + b4.y, 0.f) - fmaxf(c.y + d.y, 0.f);
            float h2 = fmaxf(a.z + b4.z, 0.f) - fmaxf(c.z + d.z, 0.f);
            float h3 = fmaxf(a.w + b4.w, 0.f) - fmaxf(c.w + d.w, 0.f);
            uint32_t hiA, loA, hiB, loB;
            bf16_split2(h0, h1, hiA, loA);
            bf16_split2(h2, h3, hiB, loB);
            int reg = (j >> 3) + 2 * bkhi;
            int lf0 = (j & 7) * 4 + 2 * blpar;          // even
            uint32_t word = (uint32_t)((bs * 4 + reg) * 32 + (lf0 ^ (4 * bs)));
            *(uint2*)(A1h + word * 4) = make_uint2(hiA, hiB);
            *(uint2*)(A1l + word * 4) = make_uint2(loA, loB);
        }
        __syncwarp();

        // ---- GEMM1: [16 x 64] += hdiff[16 x 128] @ A3[128 x 64], 3-term bf16 ----
        float acc[8][4];
#pragma unroll
        for (int nt = 0; nt < 8; nt++)
#pragma unroll
            for (int r = 0; r < 4; r++) acc[nt][r] = 0.f;
#pragma unroll
        for (int s = 0; s < 8; s++) {
            int lsw = l ^ (4 * s);
            uint32_t ah[4], al[4];
#pragma unroll
            for (int r = 0; r < 4; r++) {
                ah[r] = *(const uint32_t*)(A1h + ((s * 4 + r) * 32 + lsw) * 4);
                al[r] = *(const uint32_t*)(A1l + ((s * 4 + r) * 32 + lsw) * 4);
            }
#pragma unroll
            for (int nt = 0; nt < 8; nt++) {
                uint32_t boff = (uint32_t)((((s * 8 + nt) * 2) * 32 + l) * 4);
                uint32_t bh0 = *(const uint32_t*)(smem + SM_B1H + boff);
                uint32_t bh1 = *(const uint32_t*)(smem + SM_B1H + boff + 128);
                uint32_t bl0 = *(const uint32_t*)(smem + SM_B1L + boff);
                uint32_t bl1 = *(const uint32_t*)(smem + SM_B1L + boff + 128);
                mma_bf16(acc[nt][0], acc[nt][1], acc[nt][2], acc[nt][3],
                         ah[0], ah[1], ah[2], ah[3], bh0, bh1);
                mma_bf16(acc[nt][0], acc[nt][1], acc[nt][2], acc[nt][3],
                         al[0], al[1], al[2], al[3], bh0, bh1);
                mma_bf16(acc[nt][0], acc[nt][1], acc[nt][2], acc[nt][3],
                         ah[0], ah[1], ah[2], ah[3], bl0, bl1);
            }
        }
        __syncwarp();   // all lanes done reading A1 before overlay write

        // ---- epilogue1: relu + split -> swizzled A2 fragments (lf == lane) ----
#pragma unroll
        for (int nt = 0; nt < 8; nt++) {
            float x0 = fmaxf(acc[nt][0], 0.f), x1 = fmaxf(acc[nt][1], 0.f);
            float x2 = fmaxf(acc[nt][2], 0.f), x3 = fmaxf(acc[nt][3], 0.f);
            uint32_t hi0, lo0, hi1, lo1;
            bf16_split2(x0, x1, hi0, lo0);    // rows l>>2     -> rhi=0
            bf16_split2(x2, x3, hi1, lo1);    // rows l>>2 + 8 -> rhi=1
            int s2 = nt >> 1, khi = nt & 1;
            int lsw = l ^ (4 * s2);
            uint32_t o0 = (uint32_t)(((s2 * 4 + 2 * khi + 0) * 32 + lsw) * 4);
            uint32_t o1 = (uint32_t)(((s2 * 4 + 2 * khi + 1) * 32 + lsw) * 4);
            *(uint32_t*)(A2h + o0) = hi0;
            *(uint32_t*)(A2h + o1) = hi1;
            *(uint32_t*)(A2l + o0) = lo0;
            *(uint32_t*)(A2l + o1) = lo1;
        }
        __syncwarp();

        // ---- GEMM2: [16 x 64] += relu(d)[16 x 64] @ A4[64 x 64] ----
        float vac[8][4];
#pragma unroll
        for (int nt = 0; nt < 8; nt++)
#pragma unroll
            for (int r = 0; r < 4; r++) vac[nt][r] = 0.f;
#pragma unroll
        for (int s = 0; s < 4; s++) {
            int lsw = l ^ (4 * s);
            uint32_t ah[4], al[4];
#pragma unroll
            for (int r = 0; r < 4; r++) {
                ah[r] = *(const uint32_t*)(A2h + ((s * 4 + r) * 32 + lsw) * 4);
                al[r] = *(const uint32_t*)(A2l + ((s * 4 + r) * 32 + lsw) * 4);
            }
#pragma unroll
            for (int nt = 0; nt < 8; nt++) {
                uint32_t boff = (uint32_t)((((s * 8 + nt) * 2) * 32 + l) * 4);
                uint32_t bh0 = *(const uint32_t*)(smem + SM_B2H + boff);
                uint32_t bh1 = *(const uint32_t*)(smem + SM_B2H + boff + 128);
                uint32_t bl0 = *(const uint32_t*)(smem + SM_B2L + boff);
                uint32_t bl1 = *(const uint32_t*)(smem + SM_B2L + boff + 128);
                mma_bf16(vac[nt][0], vac[nt][1], vac[nt][2], vac[nt][3],
                         ah[0], ah[1], ah[2], ah[3], bh0, bh1);
                mma_bf16(vac[nt][0], vac[nt][1], vac[nt][2], vac[nt][3],
                         al[0], al[1], al[2], al[3], bh0, bh1);
                mma_bf16(vac[nt][0], vac[nt][1], vac[nt][2], vac[nt][3],
                         ah[0], ah[1], ah[2], ah[3], bl0, bl1);
            }
        }

        // ---- epilogue2: bias + STG ----
        {
            int g0 = tile * TILE_M + w * 16 + lr0;
            int e0 = g0 / 12, t0 = g0 - 12 * e0;
            int g1 = g0 + 8;
            int e1 = g1 / 12, t1 = g1 - 12 * e1;
            float* ob0 = outv + (size_t)e0 * TD_ + t0 * 64;
            float* ob1 = outv + (size_t)e1 * TD_ + t1 * 64;
#pragma unroll
            for (int nt = 0; nt < 8; nt++) {
                int c = nt * 8 + col0;
                float bz0 = biasSh[c], bz1 = biasSh[c + 1];
                *(float2*)(ob0 + c) = make_float2(vac[nt][0] + bz0, vac[nt][1] + bz1);
                *(float2*)(ob1 + c) = make_float2(vac[nt][2] + bz0, vac[nt][3] + bz1);
            }
        }
    }
}

// ---------------- per-sender-segment softmax (in place; no max pass) ----------------
// v_pre is analytically bounded (|v| ~ O(0.3)): plain exp is safe and exact-math
// identical to the max-subtracted form (epsilon term negligible, denom O(1)).
__global__ void k_softmax(float* __restrict__ v) {
    int seg = blockIdx.x;
    int beg = g_off[seg], end = g_off[seg + 1];
    if (beg == end) return;
    int tid = threadIdx.x;
    int c0 = tid, c1 = tid + 256, c2 = tid + 512;
    float s0 = 0.f, s1 = 0.f, s2 = 0.f;
    for (int i = beg; i < end; i++) {
        const float* vp = v + (size_t)g_csr_s[i] * TD_;
        s0 += __expf(vp[c0]); s1 += __expf(vp[c1]); s2 += __expf(vp[c2]);
    }
    float r0 = 1.f / (s0 + 1e-12f), r1 = 1.f / (s1 + 1e-12f), r2 = 1.f / (s2 + 1e-12f);
    for (int i = beg; i < end; i++) {
        float* vp = v + (size_t)g_csr_s[i] * TD_;
        vp[c0] = __expf(vp[c0]) * r0;
        vp[c1] = __expf(vp[c1]) * r1;
        vp[c2] = __expf(vp[c2]) * r2;
    }
}

// ---------------- per-receiver aggregation + x update ----------------
__global__ void k_aggregate(const float* __restrict__ x, const float* __restrict__ v,
                            const int* __restrict__ bi, const int* __restrict__ si,
                            float* __restrict__ outx) {
    int seg = blockIdx.x;
    int tid = threadIdx.x;
    int beg = g_off[(SEG_ + 1) + seg], end = g_off[(SEG_ + 1) + seg + 1];
    int c0 = tid, c1 = tid + 256, c2 = tid + 512;
    float a0 = 0.f, a1 = 0.f, a2 = 0.f;
    for (int i = beg; i < end; i++) {
        int e = g_csr_r[i];
        int ns = bi[e] * N_ + si[e];
        const float* vp = v + (size_t)e * TD_;
        const float* xs = x + (size_t)ns * TD_;
        a0 = fmaf(vp[c0], xs[c0], a0);
        a1 = fmaf(vp[c1], xs[c1], a1);
        a2 = fmaf(vp[c2], xs[c2], a2);
    }
    const float* xr = x + (size_t)seg * TD_;
    float* o = outx + (size_t)seg * TD_;
    o[c0] = xr[c0] + 0.1f * (a0 - xr[c0]);
    o[c1] = xr[c1] + 0.1f * (a1 - xr[c1]);
    o[c2] = xr[c2] + 0.1f * (a2 - xr[c2]);
}

// ---------------- launch ----------------
extern "C" void kernel_launch(void* const* d_in, const int* in_sizes, int n_in,
                              void* d_out, int out_size) {
    const float* x   = (const float*)d_in[0];
    const int*   bi  = (const int*)d_in[1];
    const int*   si  = (const int*)d_in[2];
    const int*   ri  = (const int*)d_in[3];
    const float* A1w = (const float*)d_in[4];
    const float* A1b = (const float*)d_in[5];
    const float* A2w = (const float*)d_in[6];
    const float* A2b = (const float*)d_in[7];
    const float* A3w = (const float*)d_in[8];
    // d_in[9] = A3_b: cancels in z_ij - z_ji
    const float* A4w = (const float*)d_in[10];
    const float* A4b = (const float*)d_in[11];

    float* outx = (float*)d_out;
    float* outv = outx + (size_t)ROWS_ * D_;

    const int np_smem = NP_SMEM_FLOATS * 4;
    cudaFuncSetAttribute(k_nodeproj, cudaFuncAttributeMaxDynamicSharedMemorySize, np_smem);
    cudaFuncSetAttribute(k_edge_mma, cudaFuncAttributeMaxDynamicSharedMemorySize, EM_SMEM);

    k_countscan<<<1, 1024>>>(bi, si, ri);
    k_scatter<<<(E_ + 255) / 256, 256>>>(bi, si, ri);
    k_nodeproj<<<ROWS_ / 128, 128, np_smem>>>(x, A1w, A1b, A2w, A2b);
    k_edge_mma<<<296, 256, EM_SMEM>>>(bi, si, ri, A3w, A4w, A4b, outv);
    k_softmax<<<SEG_, 256>>>(outv);
    k_aggregate<<<SEG_, 256>>>(x, outv, bi, si, outx);
}